// round 11
// baseline (speedup 1.0000x reference)
#include <cuda_runtime.h>

#define A_DIM 256
#define H_DIM 512
#define S_DIM 1024
#define T_DIM 256
#define B_DIM 4
#define MS (B_DIM * S_DIM)   /* 4096 rows of eh */
#define MT (B_DIM * T_DIM)   /* 1024 rows of dh */

__device__ float g_ehT[A_DIM * MS];   // [A][B*S]
__device__ float g_dh[MT * A_DIM];    // [B*T][A]

__device__ __forceinline__ float tanh_fast(float x) {
    float y;
    asm("tanh.approx.f32 %0, %1;" : "=f"(y) : "f"(x));
    return y;
}
__device__ __forceinline__ void ffma2(float2& d, const float2 a, const float2 b) {
    unsigned long long ud = *(const unsigned long long*)&d;
    unsigned long long ua = *(const unsigned long long*)&a;
    unsigned long long ub = *(const unsigned long long*)&b;
    asm("fma.rn.f32x2 %0, %1, %2, %0;" : "+l"(ud) : "l"(ua), "l"(ub));
    *(unsigned long long*)&d = ud;
}

// ============================================================================
// Dual GEMM: 64x64 tiles, 256 threads, 4x4/thread, double-buffered.
// X stored into smem PRE-DUPLICATED (Xd[k][2m]=Xd[k][2m+1]=X[m][k]) so the
// f32x2 FFMA operands come straight out of LDS.128 with zero dup-MOVs.
//   blockIdx.x <  64 : ehT = (enc @ Wh + bh)^T   (M=4096)
//   blockIdx.x >= 64 : dh  =  dec @ Ws + bs      (M=1024)
// ============================================================================
#define GBK 16
#define XDP 140            /* padded row stride for Xd (floats) */
#define GNSTEP (H_DIM / GBK)
__global__ __launch_bounds__(256) void dual_gemm_kernel(
    const float* __restrict__ enc, const float* __restrict__ dec,
    const float* __restrict__ Wh,  const float* __restrict__ bh,
    const float* __restrict__ Wsm, const float* __restrict__ bsm,
    float* __restrict__ ehT, float* __restrict__ dh)
{
    __shared__ float Xd[2][GBK][XDP];   // duplicated X
    __shared__ float Wt[2][GBK][64];

    bool p2 = blockIdx.x >= 64;
    const float* X    = p2 ? dec : enc;
    const float* W    = p2 ? Wsm : Wh;
    const float* bias = p2 ? bsm : bh;
    int m0 = (p2 ? (blockIdx.x - 64) : blockIdx.x) * 64;
    int n0 = blockIdx.y * 64;
    const int K = H_DIM, N = A_DIM;

    int tid  = threadIdx.x;
    int trow = (tid >> 4) * 4;   // 0..60 (m base)
    int tcol = (tid & 15) * 4;   // 0..60 (n base)

    // loader mapping
    int lm = tid >> 2;           // 0..63 (X row)
    int lk = (tid & 3) * 4;      // 0,4,8,12
    int wk = tid >> 4;           // 0..15 (W row)
    int wn = (tid & 15) * 4;     // 0..60

    const float* xptr = &X[(size_t)(m0 + lm) * K + lk];
    const float* wptr = &W[(size_t)wk * N + n0 + wn];

    float2 acc[2][4];            // [col-pair][row]
#pragma unroll
    for (int cp = 0; cp < 2; cp++)
#pragma unroll
        for (int r = 0; r < 4; r++) acc[cp][r] = make_float2(0.f, 0.f);

    // prologue: fetch + stage step 0
    float4 xv = *(const float4*)xptr;
    float4 wv = *(const float4*)wptr;
    {
        float xs[4] = {xv.x, xv.y, xv.z, xv.w};
#pragma unroll
        for (int i = 0; i < 4; i++)
            *(float2*)&Xd[0][lk + i][2 * lm] = make_float2(xs[i], xs[i]);
        *(float4*)&Wt[0][wk][wn] = wv;
    }
    __syncthreads();

    for (int step = 0; step < GNSTEP; step++) {
        int cur = step & 1;
        if (step + 1 < GNSTEP) {
            xv = *(const float4*)(xptr + (step + 1) * GBK);
            wv = *(const float4*)(wptr + (size_t)(step + 1) * GBK * N);
        }

#pragma unroll
        for (int kk = 0; kk < GBK; kk++) {
            // two LDS.128: rows (trow,trow+1) and (trow+2,trow+3), pre-dup'd
            float4 xa = *(const float4*)&Xd[cur][kk][2 * trow];
            float4 xb = *(const float4*)&Xd[cur][kk][2 * trow + 4];
            float4 w4 = *(const float4*)&Wt[cur][kk][tcol];
            float2 xd[4] = { make_float2(xa.x, xa.y), make_float2(xa.z, xa.w),
                             make_float2(xb.x, xb.y), make_float2(xb.z, xb.w) };
            float2 wp0 = make_float2(w4.x, w4.y);
            float2 wp1 = make_float2(w4.z, w4.w);
#pragma unroll
            for (int r = 0; r < 4; r++) {
                ffma2(acc[0][r], xd[r], wp0);
                ffma2(acc[1][r], xd[r], wp1);
            }
        }

        if (step + 1 < GNSTEP) {
            int nxt = cur ^ 1;
            float xs[4] = {xv.x, xv.y, xv.z, xv.w};
#pragma unroll
            for (int i = 0; i < 4; i++)
                *(float2*)&Xd[nxt][lk + i][2 * lm] = make_float2(xs[i], xs[i]);
            *(float4*)&Wt[nxt][wk][wn] = wv;
        }
        __syncthreads();
    }

    float bj[4];
#pragma unroll
    for (int j = 0; j < 4; j++) bj[j] = bias[n0 + tcol + j];

    if (!p2) {
        // transposed store: ehT[n][m]; acc[cp][r] holds cols (2cp, 2cp+1)
#pragma unroll
        for (int j = 0; j < 4; j++) {
            int cp = j >> 1;
            float c0 = (j & 1) ? acc[cp][0].y : acc[cp][0].x;
            float c1 = (j & 1) ? acc[cp][1].y : acc[cp][1].x;
            float c2 = (j & 1) ? acc[cp][2].y : acc[cp][2].x;
            float c3 = (j & 1) ? acc[cp][3].y : acc[cp][3].x;
            size_t base = (size_t)(n0 + tcol + j) * MS + m0 + trow;
            *(float4*)&ehT[base] =
                make_float4(c0 + bj[j], c1 + bj[j], c2 + bj[j], c3 + bj[j]);
        }
    } else {
#pragma unroll
        for (int r = 0; r < 4; r++) {
            float4 v = make_float4(acc[0][r].x + bj[0], acc[0][r].y + bj[1],
                                   acc[1][r].x + bj[2], acc[1][r].y + bj[3]);
            *(float4*)&dh[(size_t)(m0 + trow + r) * A_DIM + n0 + tcol] = v;
        }
    }
}

// ============================================================================
// Persistent attn+softmax (proven: 66.8us, rel_err 2.85e-6).
// 148 CTAs = 4 x 37; 1024 threads (thread = one s); 7|6 t padded to 8 slots.
// bv dropped (softmax-invariant).
// ============================================================================
#define CTAS_PER_B 37
#define NT_MAX 7
__global__ __launch_bounds__(1024, 1) void attn_softmax_kernel(
    const float* __restrict__ Wv, float* __restrict__ out)
{
    __shared__ float sdh[A_DIM][8];
    __shared__ float swv[A_DIM];
    __shared__ float redm[32 * 8];
    __shared__ float bmax[8];
    __shared__ float bsum[8];

    int b   = blockIdx.x / CTAS_PER_B;
    int idx = blockIdx.x % CTAS_PER_B;
    int t0, nt;
    if (idx < 34) { t0 = idx * 7;              nt = 7; }
    else          { t0 = 238 + (idx - 34) * 6; nt = 6; }

    int tid = threadIdx.x;
    for (int i = tid; i < A_DIM * 8; i += 1024) {
        int a = i >> 3, t = i & 7;
        int tt = t < nt ? t : nt - 1;
        sdh[a][t] = g_dh[(size_t)(b * T_DIM + t0 + tt) * A_DIM + a];
    }
    if (tid < A_DIM) swv[tid] = Wv[tid];
    __syncthreads();

    int w = tid >> 5, l = tid & 31;
    const float* ehp = &g_ehT[(size_t)b * S_DIM + tid];

    float acc[NT_MAX];
#pragma unroll
    for (int t = 0; t < NT_MAX; t++) acc[t] = 0.f;

#pragma unroll 4
    for (int a = 0; a < A_DIM; a++) {
        float e  = __ldg(ehp + (size_t)a * MS);
        float wv = swv[a];
        float4 d0 = *(const float4*)&sdh[a][0];
        float4 d1 = *(const float4*)&sdh[a][4];
        acc[0] += wv * tanh_fast(e + d0.x);
        acc[1] += wv * tanh_fast(e + d0.y);
        acc[2] += wv * tanh_fast(e + d0.z);
        acc[3] += wv * tanh_fast(e + d0.w);
        acc[4] += wv * tanh_fast(e + d1.x);
        acc[5] += wv * tanh_fast(e + d1.y);
        acc[6] += wv * tanh_fast(e + d1.z);
    }

    // ---- per-t block max
#pragma unroll
    for (int t = 0; t < NT_MAX; t++) {
        float m = acc[t];
#pragma unroll
        for (int o = 16; o > 0; o >>= 1) m = fmaxf(m, __shfl_xor_sync(0xffffffffu, m, o));
        if (l == 0) redm[w * 8 + t] = m;
    }
    __syncthreads();
    if (w < NT_MAX) {
        float m = redm[l * 8 + w];
#pragma unroll
        for (int o = 16; o > 0; o >>= 1) m = fmaxf(m, __shfl_xor_sync(0xffffffffu, m, o));
        if (l == 0) bmax[w] = m;
    }
    __syncthreads();

    // ---- exp + per-t block sum
    float ex[NT_MAX];
#pragma unroll
    for (int t = 0; t < NT_MAX; t++) {
        ex[t] = __expf(acc[t] - bmax[t]);
        float s = ex[t];
#pragma unroll
        for (int o = 16; o > 0; o >>= 1) s += __shfl_xor_sync(0xffffffffu, s, o);
        if (l == 0) redm[w * 8 + t] = s;
    }
    __syncthreads();
    if (w < NT_MAX) {
        float s = redm[l * 8 + w];
#pragma unroll
        for (int o = 16; o > 0; o >>= 1) s += __shfl_xor_sync(0xffffffffu, s, o);
        if (l == 0) bsum[w] = s;
    }
    __syncthreads();

#pragma unroll
    for (int t = 0; t < NT_MAX; t++) {
        if (t < nt)
            out[(size_t)(b * T_DIM + t0 + t) * S_DIM + tid] = ex[t] * (1.f / bsum[t]);
    }
}

extern "C" void kernel_launch(void* const* d_in, const int* in_sizes, int n_in,
                              void* d_out, int out_size)
{
    const float* enc = (const float*)d_in[0];  // [4,1024,512]
    const float* dec = (const float*)d_in[1];  // [4,256,512]
    const float* Wh  = (const float*)d_in[2];  // [512,256]
    const float* bh  = (const float*)d_in[3];  // [256]
    const float* Ws  = (const float*)d_in[4];  // [512,256]
    const float* bs  = (const float*)d_in[5];  // [256]
    const float* Wv  = (const float*)d_in[6];  // [256,1]
    // d_in[7] = bv: softmax-invariant shift, unused.
    float* out = (float*)d_out;                // [4,256,1024]

    float* ehT;
    float* dh;
    cudaGetSymbolAddress((void**)&ehT, g_ehT);
    cudaGetSymbolAddress((void**)&dh, g_dh);

    dim3 g1(64 + 16, A_DIM / 64);              // 320 CTAs, both GEMMs
    dual_gemm_kernel<<<g1, 256>>>(enc, dec, Wh, bh, Ws, bs, ehT, dh);

    attn_softmax_kernel<<<B_DIM * CTAS_PER_B, 1024>>>(Wv, out);   // 148 CTAs
}

// round 17
// speedup vs baseline: 1.1601x; 1.1601x over previous
#include <cuda_runtime.h>
#include <cstdint>

#define A_DIM 256
#define H_DIM 512
#define S_DIM 1024
#define T_DIM 256
#define B_DIM 4
#define MS (B_DIM * S_DIM)   /* 4096 rows of eh */
#define MT (B_DIM * T_DIM)   /* 1024 rows of dh */

__device__ float g_ehT[A_DIM * MS];   // [A][B*S]
__device__ float g_dh[MT * A_DIM];    // [B*T][A]

__device__ __forceinline__ float tanh_fast(float x) {
    float y;
    asm("tanh.approx.f32 %0, %1;" : "=f"(y) : "f"(x));
    return y;
}
__device__ __forceinline__ uint32_t f2tf(float x) {
    uint32_t r;
    asm("cvt.rna.tf32.f32 %0, %1;" : "=r"(r) : "f"(x));
    return r;
}
__device__ __forceinline__ void mma_tf32(float4& c, const uint32_t* a, const uint32_t* b) {
    asm("mma.sync.aligned.m16n8k8.row.col.f32.tf32.tf32.f32 "
        "{%0,%1,%2,%3},{%4,%5,%6,%7},{%8,%9},{%0,%1,%2,%3};"
        : "+f"(c.x), "+f"(c.y), "+f"(c.z), "+f"(c.w)
        : "r"(a[0]), "r"(a[1]), "r"(a[2]), "r"(a[3]), "r"(b[0]), "r"(b[1]));
}

// ============================================================================
// Dual GEMM via 3xTF32 tensor-core MMA (fp32-grade accuracy).
// C = X[M,512] @ W[512,256] + bias. BM=64, BN=64, BK=32, 256 thr (8 warps,
// 2x4), warp tile 32x16 (2 m-atoms x 2 n-atoms of m16n8k8).
//   blockIdx.x <  64 : ehT = (enc @ Wh + bh)^T   (M=4096)
//   blockIdx.x >= 64 : dh  =  dec @ Ws + bs      (M=1024)
// hi/lo split done at STS time; D += al*bh + ah*bl + ah*bh.
// Pads: X rows 36 (A-frag LDS conflict-free), W rows 72 (B-frag conflict-free).
// ============================================================================
#define GBK 32
#define NSTEP (H_DIM / GBK)   /* 16 */
__global__ __launch_bounds__(256) void dual_gemm_tc(
    const float* __restrict__ enc, const float* __restrict__ dec,
    const float* __restrict__ Wh,  const float* __restrict__ bh,
    const float* __restrict__ Wsm, const float* __restrict__ bsm,
    float* __restrict__ ehT, float* __restrict__ dh)
{
    __shared__ uint32_t Xhi[64][36], Xlo[64][36];
    __shared__ uint32_t Whi[GBK][72], Wlo[GBK][72];

    bool p2 = blockIdx.x >= 64;
    const float* X    = p2 ? dec : enc;
    const float* W    = p2 ? Wsm : Wh;
    const float* bias = p2 ? bsm : bh;
    int m0 = (p2 ? (blockIdx.x - 64) : blockIdx.x) * 64;
    int n0 = blockIdx.y * 64;

    int tid  = threadIdx.x;
    int wid  = tid >> 5;
    int lane = tid & 31;
    int gid  = lane >> 2;        // 0..7
    int tg   = lane & 3;         // 0..3
    int wm   = (wid >> 2) * 32;  // warp m offset: 0 or 32
    int wn   = (wid & 3) * 16;   // warp n offset: 0..48

    // loader mapping
    int lm  = tid >> 2;          // 0..63  X row
    int lk8 = (tid & 3) * 8;     // 0,8,16,24
    int wk  = tid >> 3;          // 0..31  W row (k)
    int wn8 = (tid & 7) * 8;     // 0..56

    const float* xptr = &X[(size_t)(m0 + lm) * H_DIM + lk8];
    const float* wptr = &W[(size_t)wk * A_DIM + n0 + wn8];

    float4 acc[2][2];
#pragma unroll
    for (int i = 0; i < 2; i++)
#pragma unroll
        for (int j = 0; j < 2; j++) acc[i][j] = make_float4(0.f, 0.f, 0.f, 0.f);

    // prefetch step 0
    float4 sx0 = *(const float4*)xptr;
    float4 sx1 = *(const float4*)(xptr + 4);
    float4 sw0 = *(const float4*)wptr;
    float4 sw1 = *(const float4*)(wptr + 4);

    for (int step = 0; step < NSTEP; step++) {
        if (step) __syncthreads();   // buffer free (consumers of prev step done)

        // ---- split + STS ----
        {
            float xs[8] = {sx0.x, sx0.y, sx0.z, sx0.w, sx1.x, sx1.y, sx1.z, sx1.w};
            uint32_t hv[8], lv[8];
#pragma unroll
            for (int i = 0; i < 8; i++) {
                hv[i] = f2tf(xs[i]);
                lv[i] = f2tf(xs[i] - __uint_as_float(hv[i]));
            }
            *(uint4*)&Xhi[lm][lk8]     = make_uint4(hv[0], hv[1], hv[2], hv[3]);
            *(uint4*)&Xhi[lm][lk8 + 4] = make_uint4(hv[4], hv[5], hv[6], hv[7]);
            *(uint4*)&Xlo[lm][lk8]     = make_uint4(lv[0], lv[1], lv[2], lv[3]);
            *(uint4*)&Xlo[lm][lk8 + 4] = make_uint4(lv[4], lv[5], lv[6], lv[7]);

            float ws[8] = {sw0.x, sw0.y, sw0.z, sw0.w, sw1.x, sw1.y, sw1.z, sw1.w};
#pragma unroll
            for (int i = 0; i < 8; i++) {
                hv[i] = f2tf(ws[i]);
                lv[i] = f2tf(ws[i] - __uint_as_float(hv[i]));
            }
            *(uint4*)&Whi[wk][wn8]     = make_uint4(hv[0], hv[1], hv[2], hv[3]);
            *(uint4*)&Whi[wk][wn8 + 4] = make_uint4(hv[4], hv[5], hv[6], hv[7]);
            *(uint4*)&Wlo[wk][wn8]     = make_uint4(lv[0], lv[1], lv[2], lv[3]);
            *(uint4*)&Wlo[wk][wn8 + 4] = make_uint4(lv[4], lv[5], lv[6], lv[7]);
        }
        __syncthreads();

        // ---- prefetch next step ----
        if (step + 1 < NSTEP) {
            const float* xp = xptr + (step + 1) * GBK;
            sx0 = *(const float4*)xp;
            sx1 = *(const float4*)(xp + 4);
            const float* wp = wptr + (size_t)(step + 1) * GBK * A_DIM;
            sw0 = *(const float4*)wp;
            sw1 = *(const float4*)(wp + 4);
        }

        // ---- compute: 4 k-atoms of 8 ----
#pragma unroll
        for (int ka = 0; ka < 4; ka++) {
            int kb = ka * 8;
            uint32_t ah[2][4], al[2][4];
#pragma unroll
            for (int ma = 0; ma < 2; ma++) {
                int r = wm + ma * 16 + gid;
                ah[ma][0] = Xhi[r][kb + tg];
                ah[ma][1] = Xhi[r + 8][kb + tg];
                ah[ma][2] = Xhi[r][kb + tg + 4];
                ah[ma][3] = Xhi[r + 8][kb + tg + 4];
                al[ma][0] = Xlo[r][kb + tg];
                al[ma][1] = Xlo[r + 8][kb + tg];
                al[ma][2] = Xlo[r][kb + tg + 4];
                al[ma][3] = Xlo[r + 8][kb + tg + 4];
            }
            uint32_t bhf[2][2], blf[2][2];
#pragma unroll
            for (int na = 0; na < 2; na++) {
                int cn = wn + na * 8 + gid;
                bhf[na][0] = Whi[kb + tg][cn];
                bhf[na][1] = Whi[kb + tg + 4][cn];
                blf[na][0] = Wlo[kb + tg][cn];
                blf[na][1] = Wlo[kb + tg + 4][cn];
            }
#pragma unroll
            for (int ma = 0; ma < 2; ma++)
#pragma unroll
                for (int na = 0; na < 2; na++) {
                    mma_tf32(acc[ma][na], al[ma], bhf[na]);
                    mma_tf32(acc[ma][na], ah[ma], blf[na]);
                    mma_tf32(acc[ma][na], ah[ma], bhf[na]);
                }
        }
    }

    // ---- epilogue ----
#pragma unroll
    for (int ma = 0; ma < 2; ma++) {
#pragma unroll
        for (int na = 0; na < 2; na++) {
            float4 c = acc[ma][na];
            int m = m0 + wm + ma * 16 + gid;
            int n = n0 + wn + na * 8 + 2 * tg;
            float b0 = bias[n], b1 = bias[n + 1];
            if (!p2) {
                // ehT[n][m]: lanes with equal tg cover 8 consecutive m -> coalesced
                g_ehT[(size_t)n * MS + m]           = c.x + b0;
                g_ehT[(size_t)(n + 1) * MS + m]     = c.y + b1;
                g_ehT[(size_t)n * MS + m + 8]       = c.z + b0;
                g_ehT[(size_t)(n + 1) * MS + m + 8] = c.w + b1;
            } else {
                *(float2*)&g_dh[(size_t)m * A_DIM + n]       = make_float2(c.x + b0, c.y + b1);
                *(float2*)&g_dh[(size_t)(m + 8) * A_DIM + n] = make_float2(c.z + b0, c.w + b1);
            }
        }
    }
}

// ============================================================================
// Persistent attn+softmax (proven: ~67us, rel_err 2.85e-6). Unchanged.
// ============================================================================
#define CTAS_PER_B 37
#define NT_MAX 7
__global__ __launch_bounds__(1024, 1) void attn_softmax_kernel(
    const float* __restrict__ Wv, float* __restrict__ out)
{
    __shared__ float sdh[A_DIM][8];
    __shared__ float swv[A_DIM];
    __shared__ float redm[32 * 8];
    __shared__ float bmax[8];
    __shared__ float bsum[8];

    int b   = blockIdx.x / CTAS_PER_B;
    int idx = blockIdx.x % CTAS_PER_B;
    int t0, nt;
    if (idx < 34) { t0 = idx * 7;              nt = 7; }
    else          { t0 = 238 + (idx - 34) * 6; nt = 6; }

    int tid = threadIdx.x;
    for (int i = tid; i < A_DIM * 8; i += 1024) {
        int a = i >> 3, t = i & 7;
        int tt = t < nt ? t : nt - 1;
        sdh[a][t] = g_dh[(size_t)(b * T_DIM + t0 + tt) * A_DIM + a];
    }
    if (tid < A_DIM) swv[tid] = Wv[tid];
    __syncthreads();

    int w = tid >> 5, l = tid & 31;
    const float* ehp = &g_ehT[(size_t)b * S_DIM + tid];

    float acc[NT_MAX];
#pragma unroll
    for (int t = 0; t < NT_MAX; t++) acc[t] = 0.f;

#pragma unroll 4
    for (int a = 0; a < A_DIM; a++) {
        float e  = __ldg(ehp + (size_t)a * MS);
        float wv = swv[a];
        float4 d0 = *(const float4*)&sdh[a][0];
        float4 d1 = *(const float4*)&sdh[a][4];
        acc[0] += wv * tanh_fast(e + d0.x);
        acc[1] += wv * tanh_fast(e + d0.y);
        acc[2] += wv * tanh_fast(e + d0.z);
        acc[3] += wv * tanh_fast(e + d0.w);
        acc[4] += wv * tanh_fast(e + d1.x);
        acc[5] += wv * tanh_fast(e + d1.y);
        acc[6] += wv * tanh_fast(e + d1.z);
    }

#pragma unroll
    for (int t = 0; t < NT_MAX; t++) {
        float m = acc[t];
#pragma unroll
        for (int o = 16; o > 0; o >>= 1) m = fmaxf(m, __shfl_xor_sync(0xffffffffu, m, o));
        if (l == 0) redm[w * 8 + t] = m;
    }
    __syncthreads();
    if (w < NT_MAX) {
        float m = redm[l * 8 + w];
#pragma unroll
        for (int o = 16; o > 0; o >>= 1) m = fmaxf(m, __shfl_xor_sync(0xffffffffu, m, o));
        if (l == 0) bmax[w] = m;
    }
    __syncthreads();

    float ex[NT_MAX];
#pragma unroll
    for (int t = 0; t < NT_MAX; t++) {
        ex[t] = __expf(acc[t] - bmax[t]);
        float s = ex[t];
#pragma unroll
        for (int o = 16; o > 0; o >>= 1) s += __shfl_xor_sync(0xffffffffu, s, o);
        if (l == 0) redm[w * 8 + t] = s;
    }
    __syncthreads();
    if (w < NT_MAX) {
        float s = redm[l * 8 + w];
#pragma unroll
        for (int o = 16; o > 0; o >>= 1) s += __shfl_xor_sync(0xffffffffu, s, o);
        if (l == 0) bsum[w] = s;
    }
    __syncthreads();

#pragma unroll
    for (int t = 0; t < NT_MAX; t++) {
        if (t < nt)
            out[(size_t)(b * T_DIM + t0 + t) * S_DIM + tid] = ex[t] * (1.f / bsum[t]);
    }
}

extern "C" void kernel_launch(void* const* d_in, const int* in_sizes, int n_in,
                              void* d_out, int out_size)
{
    const float* enc = (const float*)d_in[0];  // [4,1024,512]
    const float* dec = (const float*)d_in[1];  // [4,256,512]
    const float* Wh  = (const float*)d_in[2];  // [512,256]
    const float* bh  = (const float*)d_in[3];  // [256]
    const float* Ws  = (const float*)d_in[4];  // [512,256]
    const float* bs  = (const float*)d_in[5];  // [256]
    const float* Wv  = (const float*)d_in[6];  // [256,1]
    // d_in[7] = bv: softmax-invariant shift, unused.
    float* out = (float*)d_out;                // [4,256,1024]

    float* ehT;
    float* dh;
    cudaGetSymbolAddress((void**)&ehT, g_ehT);
    cudaGetSymbolAddress((void**)&dh, g_dh);

    dim3 g1(64 + 16, A_DIM / 64);              // 320 CTAs, both GEMMs
    dual_gemm_tc<<<g1, 256>>>(enc, dec, Wh, bh, Ws, bs, ehT, dh);

    attn_softmax_kernel<<<B_DIM * CTAS_PER_B, 1024>>>(Wv, out);   // 148 CTAs
}